// round 15
// baseline (speedup 1.0000x reference)
#include <cuda_runtime.h>
#include <cuda_fp16.h>

#define DM   2048
#define DI   4096
#define MTOT 8192

// h is stored scaled by 256 so GEMM2's fp16 products stay in normal range.
#define HSCALE 256.0f
#define HINV   (1.0f / 256.0f)

// ---------------- scratch (device globals; runtime allocs forbidden) ------
__device__ __align__(128) __half g_xn  [(size_t)MTOT * DM];
__device__ __align__(128) __half g_win [(size_t)2 * DI * DM];
__device__ __align__(128) __half g_wout[(size_t)DM * DI];
__device__ __align__(128) __half g_h   [(size_t)MTOT * DI];   // = 256 * true h
__device__ float g_dtw[DI];

// ---------------- helpers --------------------------------------------------
__device__ __forceinline__ unsigned smem_u32(const void* p) {
    unsigned a;
    asm("{ .reg .u64 t; cvta.to.shared.u64 t, %1; cvt.u32.u64 %0, t; }" : "=r"(a) : "l"(p));
    return a;
}
__device__ __forceinline__ void cp16(unsigned s, const void* g) {
    asm volatile("cp.async.cg.shared.global [%0], [%1], 16;" :: "r"(s), "l"(g));
}
#define CP_COMMIT() asm volatile("cp.async.commit_group;" ::: "memory")
#define CP_WAIT(n)  asm volatile("cp.async.wait_group %0;" :: "n"(n) : "memory")

#define SWZ(o) ((unsigned)(o) ^ ((((unsigned)(o)) >> 3) & 0x70u))

__device__ __forceinline__ void ldsm4(unsigned (&r)[4], unsigned a) {
    asm volatile("ldmatrix.sync.aligned.m8n8.x4.shared.b16 {%0,%1,%2,%3}, [%4];"
        : "=r"(r[0]), "=r"(r[1]), "=r"(r[2]), "=r"(r[3]) : "r"(a));
}
// fp16 MMA with fp16 accumulate: 2 acc regs
__device__ __forceinline__ void mma16816h(unsigned (&c)[2], const unsigned (&a)[4],
                                          unsigned b0, unsigned b1) {
    asm volatile(
        "mma.sync.aligned.m16n8k16.row.col.f16.f16.f16.f16 "
        "{%0,%1}, {%2,%3,%4,%5}, {%6,%7}, {%0,%1};"
        : "+r"(c[0]), "+r"(c[1])
        : "r"(a[0]), "r"(a[1]), "r"(a[2]), "r"(a[3]), "r"(b0), "r"(b1));
}
__device__ __forceinline__ unsigned pk2h(float a, float b) {
    __half2 t = __floats2half2_rn(a, b);
    return *reinterpret_cast<unsigned*>(&t);
}
__device__ __forceinline__ float2 up2h(unsigned u) {
    return __half22float2(*reinterpret_cast<__half2*>(&u));
}
__device__ __forceinline__ float fsig(float v) {
    v = fminf(fmaxf(v, -15.f), 15.f);
    return 1.f / (1.f + __expf(-v));
}

// ---------------- prep kernels --------------------------------------------
__global__ void ln_kernel(const float* __restrict__ x,
                          const float* __restrict__ gamma,
                          const float* __restrict__ beta) {
    __shared__ float sred[16];
    __shared__ float s_mu, s_inv;
    int row = blockIdx.x, tid = threadIdx.x;
    const float4* xr = (const float4*)(x + (size_t)row * DM);
    float4 a = xr[tid], b = xr[tid + 256];
    float s = a.x + a.y + a.z + a.w + b.x + b.y + b.z + b.w;
    float q = a.x*a.x + a.y*a.y + a.z*a.z + a.w*a.w
            + b.x*b.x + b.y*b.y + b.z*b.z + b.w*b.w;
    for (int o = 16; o; o >>= 1) {
        s += __shfl_xor_sync(~0u, s, o);
        q += __shfl_xor_sync(~0u, q, o);
    }
    if ((tid & 31) == 0) { sred[tid >> 5] = s; sred[8 + (tid >> 5)] = q; }
    __syncthreads();
    if (tid == 0) {
        float S = 0.f, Q = 0.f;
        for (int i = 0; i < 8; i++) { S += sred[i]; Q += sred[8 + i]; }
        float mu = S / DM;
        s_mu = mu;
        s_inv = rsqrtf(Q / DM - mu * mu + 1e-5f);
    }
    __syncthreads();
    float mu = s_mu, inv = s_inv;
    float4 g0 = ((const float4*)gamma)[tid],       b0 = ((const float4*)beta)[tid];
    float4 g1 = ((const float4*)gamma)[tid + 256], b1 = ((const float4*)beta)[tid + 256];
    unsigned* dst = (unsigned*)(g_xn + (size_t)row * DM);
    float nx = (a.x - mu) * inv * g0.x + b0.x, ny = (a.y - mu) * inv * g0.y + b0.y;
    float nz = (a.z - mu) * inv * g0.z + b0.z, nw = (a.w - mu) * inv * g0.w + b0.w;
    dst[tid * 2]     = pk2h(nx, ny);
    dst[tid * 2 + 1] = pk2h(nz, nw);
    nx = (b.x - mu) * inv * g1.x + b1.x; ny = (b.y - mu) * inv * g1.y + b1.y;
    nz = (b.z - mu) * inv * g1.z + b1.z; nw = (b.w - mu) * inv * g1.w + b1.w;
    dst[(tid + 256) * 2]     = pk2h(nx, ny);
    dst[(tid + 256) * 2 + 1] = pk2h(nz, nw);
}

__global__ void cvt_kernel(const float* __restrict__ src, int which, int n4) {
    __half* dst = which ? g_win : g_wout;
    int i = blockIdx.x * blockDim.x + threadIdx.x;
    if (i < n4) {
        float4 f = ((const float4*)src)[i];
        uint2 o;
        o.x = pk2h(f.x, f.y);
        o.y = pk2h(f.z, f.w);
        ((uint2*)dst)[i] = o;
    }
}

__global__ void dts_kernel(const float* __restrict__ dt) {
    __shared__ float red[32];
    __shared__ float s_m, s_s;
    int tid = threadIdx.x;
    float m = -1e30f;
    for (int i = tid; i < DI; i += 1024) m = fmaxf(m, -dt[i]);
    for (int o = 16; o; o >>= 1) m = fmaxf(m, __shfl_xor_sync(~0u, m, o));
    if ((tid & 31) == 0) red[tid >> 5] = m;
    __syncthreads();
    if (tid == 0) {
        float M = -1e30f;
        for (int i = 0; i < 32; i++) M = fmaxf(M, red[i]);
        s_m = M;
    }
    __syncthreads();
    float M = s_m, s = 0.f;
    for (int i = tid; i < DI; i += 1024) s += __expf(-dt[i] - M);
    for (int o = 16; o; o >>= 1) s += __shfl_xor_sync(~0u, s, o);
    if ((tid & 31) == 0) red[tid >> 5] = s;
    __syncthreads();
    if (tid == 0) {
        float S = 0.f;
        for (int i = 0; i < 32; i++) S += red[i];
        s_s = S;
    }
    __syncthreads();
    float inv = 1.f / s_s;
    for (int i = tid; i < DI; i += 1024) g_dtw[i] = __expf(-dt[i] - M) * inv;
}

// ---------------- fp16 mma.sync GEMMs (fp16 accumulate) -------------------
// CTA tile 256M x (64N z + 64N gate | 128N). Stage = 48 KB (BK = 64, SW128):
//   A: 256 rows @0 (32K);  B: 128 rows @32768 (16K)
//     FUSED : B rows 0-63 = W_in z rows n0.., rows 64-127 = gate rows n0..
//     !FUSED: B rows = W_out rows n0..n0+127
// 2 stages = 96 KB -> 2 CTAs/SM. Warps 4(m) x 2(n): MT=4, NT=8
//   -> 128 B LDSM traffic per HMMA (crossbar ~30% of tensor cycles).
// One __syncthreads per k-iter; load of kb+1 issued after it (stage reuse safe).
#define NSTAGE 2
#define STAGEB 49152u

// FUSED=true : h[256 x 64] = 256 * z*sig(clamp z)*dtw * gc*sig(gc)  (fp16 out)
// FUSED=false: out[256 x 128] = (h @ W_out^T)/256 + x               (fp32 out)
template <bool FUSED>
__global__ void __launch_bounds__(256, 2)
gemm_kernel(const float* __restrict__ xres, float* __restrict__ out) {
    extern __shared__ char smem[];
    const unsigned sbase = smem_u32(smem);
    __shared__ float s_dtw[64];

    const int tid = threadIdx.x, wid = tid >> 5, lane = tid & 31;
    const int wm = wid & 3;          // 4 warp-rows (64 M each)
    const int wn = wid >> 2;         // 2 warp-cols
    const int m0 = blockIdx.y * 256;
    const int n0 = blockIdx.x * (FUSED ? 64 : 128);
    const int KIT = FUSED ? (DM / 64) : (DI / 64);
    const int ldA = FUSED ? DM : DI;
    const __half* A  = FUSED ? g_xn : g_h;
    const __half* B0 = FUSED ? g_win : g_wout;
    const __half* B1 = g_win + (size_t)DI * DM;          // gate half of W_in

    if (FUSED && tid < 64) s_dtw[tid] = g_dtw[n0 + tid];

    // acc[mt][nt]: FUSED nt 0-3 = z, nt 4-7 = gate; !FUSED nt 0-7 = out cols
    unsigned acc[4][8][2];
    #pragma unroll
    for (int mt = 0; mt < 4; mt++)
        #pragma unroll
        for (int nt = 0; nt < 8; nt++) { acc[mt][nt][0] = 0u; acc[mt][nt][1] = 0u; }

    auto load_stage = [&](int s, int kb) {
        unsigned sb = sbase + (unsigned)s * STAGEB;
        int k0 = kb * 64;
        #pragma unroll
        for (int i = tid; i < 3072; i += 256) {
            if (i < 2048) {                       // A: 256 rows x 8 chunks
                int r = i >> 3, c = i & 7;
                cp16(sb + SWZ(r * 128 + c * 16),
                     A + (size_t)(m0 + r) * ldA + k0 + c * 8);
            } else {                              // B: 128 rows
                int j = i - 2048, r = j >> 3, c = j & 7;
                const __half* src;
                if (FUSED)
                    src = (r < 64) ? (B0 + (size_t)(n0 + r) * DM)
                                   : (B1 + (size_t)(n0 + r - 64) * DM);
                else
                    src = B0 + (size_t)(n0 + r) * DI;
                cp16(sb + 32768u + SWZ(r * 128 + c * 16), src + k0 + c * 8);
            }
        }
        CP_COMMIT();
    };

    load_stage(0, 0);

    // ldmatrix lane-address components (k-half select applied inside SWZ;
    // pre-swizzle offsets have bit4 == 0 so the +16 is carry-free)
    const int arow = (lane & 7) + (lane & 8);                 // A: 16 rows
    const unsigned acsel = (unsigned)(lane >> 4) << 4;        // A: k-half
    const int brow = (lane & 7) + ((lane >> 4) << 3);         // B: 16 rows (2 n-tiles)
    const unsigned bcsel = (unsigned)((lane >> 3) & 1) << 4;  // B: k-half

    for (int kb = 0; kb < KIT; kb++) {
        CP_WAIT(0);                  // stage kb data resident
        __syncthreads();             // + all warps done reading stage (kb+1)&1
        if (kb + 1 < KIT) load_stage((kb + 1) & 1, kb + 1);

        unsigned sb = sbase + (unsigned)(kb & 1) * STAGEB;
        unsigned sB = sb + 32768u;
        #pragma unroll
        for (int kc = 0; kc < 4; kc++) {
            unsigned a[4][4];
            #pragma unroll
            for (int mt = 0; mt < 4; mt++)
                ldsm4(a[mt], sb + SWZ((unsigned)((wm * 64 + mt * 16 + arow) * 128
                                                 + kc * 32) + acsel));
            if (FUSED) {
                // z: rows wn*32+p*16, gate: +64 rows; each ldsm4 covers 2 n-tiles
                unsigned bz[2][4], bg[2][4];
                #pragma unroll
                for (int p = 0; p < 2; p++) {
                    ldsm4(bz[p], sB + SWZ((unsigned)((wn * 32 + p * 16 + brow) * 128
                                                     + kc * 32) + bcsel));
                    ldsm4(bg[p], sB + SWZ((unsigned)((64 + wn * 32 + p * 16 + brow) * 128
                                                     + kc * 32) + bcsel));
                }
                #pragma unroll
                for (int mt = 0; mt < 4; mt++)
                    #pragma unroll
                    for (int p = 0; p < 2; p++) {
                        mma16816h(acc[mt][p * 2],         a[mt], bz[p][0], bz[p][1]);
                        mma16816h(acc[mt][p * 2 + 1],     a[mt], bz[p][2], bz[p][3]);
                        mma16816h(acc[mt][4 + p * 2],     a[mt], bg[p][0], bg[p][1]);
                        mma16816h(acc[mt][4 + p * 2 + 1], a[mt], bg[p][2], bg[p][3]);
                    }
            } else {
                unsigned bq[4][4];
                #pragma unroll
                for (int p = 0; p < 4; p++)
                    ldsm4(bq[p], sB + SWZ((unsigned)((wn * 64 + p * 16 + brow) * 128
                                                     + kc * 32) + bcsel));
                #pragma unroll
                for (int mt = 0; mt < 4; mt++)
                    #pragma unroll
                    for (int p = 0; p < 4; p++) {
                        mma16816h(acc[mt][p * 2],     a[mt], bq[p][0], bq[p][1]);
                        mma16816h(acc[mt][p * 2 + 1], a[mt], bq[p][2], bq[p][3]);
                    }
            }
        }
    }

    // ---------------- epilogue ---------------------------------------------
    const int mrow = (lane >> 2);
    const int ncol = (lane & 3) * 2;
    if (FUSED) {
        #pragma unroll
        for (int mt = 0; mt < 4; mt++)
            #pragma unroll
            for (int nt = 0; nt < 4; nt++) {
                int nl = wn * 32 + nt * 8 + ncol;
                float w0 = s_dtw[nl] * HSCALE, w1 = s_dtw[nl + 1] * HSCALE;
                #pragma unroll
                for (int h = 0; h < 2; h++) {
                    int m = m0 + wm * 64 + mt * 16 + mrow + h * 8;
                    float2 zv = up2h(acc[mt][nt][h]);
                    float2 gv = up2h(acc[mt][nt + 4][h]);
                    float gc0 = fminf(fmaxf(gv.x, -15.f), 15.f);
                    float gc1 = fminf(fmaxf(gv.y, -15.f), 15.f);
                    float v0 = zv.x * fsig(zv.x) * w0 * gc0 * fsig(gc0);
                    float v1 = zv.y * fsig(zv.y) * w1 * gc1 * fsig(gc1);
                    *(unsigned*)(g_h + (size_t)m * DI + n0 + nl) = pk2h(v0, v1);
                }
            }
    } else {
        #pragma unroll
        for (int mt = 0; mt < 4; mt++)
            #pragma unroll
            for (int nt = 0; nt < 8; nt++) {
                int n = n0 + wn * 64 + nt * 8 + ncol;
                #pragma unroll
                for (int h = 0; h < 2; h++) {
                    int m = m0 + wm * 64 + mt * 16 + mrow + h * 8;
                    const float2 xv = *(const float2*)(xres + (size_t)m * DM + n);
                    float2 cv = up2h(acc[mt][nt][h]);
                    float2 o;
                    o.x = cv.x * HINV + xv.x;
                    o.y = cv.y * HINV + xv.y;
                    *(float2*)(out + (size_t)m * DM + n) = o;
                }
            }
    }
}

// ---------------- launch ----------------------------------------------------
extern "C" void kernel_launch(void* const* d_in, const int* in_sizes, int n_in,
                              void* d_out, int out_size) {
    const float* x     = (const float*)d_in[0];
    const float* gamma = (const float*)d_in[1];
    const float* beta  = (const float*)d_in[2];
    const float* W_in  = (const float*)d_in[3];
    const float* W_out = (const float*)d_in[4];
    const float* dt    = (const float*)d_in[5];
    float* out = (float*)d_out;

    ln_kernel<<<MTOT, 256>>>(x, gamma, beta);
    {
        int n4 = 2 * DI * DM / 4;
        cvt_kernel<<<(n4 + 255) / 256, 256>>>(W_in, 1, n4);
    }
    {
        int n4 = DM * DI / 4;
        cvt_kernel<<<(n4 + 255) / 256, 256>>>(W_out, 0, n4);
    }
    dts_kernel<<<1, 1024>>>(dt);

    const unsigned smem = NSTAGE * STAGEB;   // 96 KB
    static int attr_done = 0;                 // never during graph capture
    if (!attr_done) {
        cudaFuncSetAttribute(gemm_kernel<true>,
                             cudaFuncAttributeMaxDynamicSharedMemorySize, smem);
        cudaFuncSetAttribute(gemm_kernel<false>,
                             cudaFuncAttributeMaxDynamicSharedMemorySize, smem);
        attr_done = 1;
    }

    gemm_kernel<true ><<<dim3(DI / 64, MTOT / 256), 256, smem>>>(nullptr, nullptr);
    gemm_kernel<false><<<dim3(DM / 128, MTOT / 256), 256, smem>>>(x, out);
}